// round 1
// baseline (speedup 1.0000x reference)
#include <cuda_runtime.h>
#include <math.h>
#include <float.h>

#define Bsz 4
#define Npt 4096
#define KNN 20
#define EPSBN 1e-5f

// ---------------- scratch (device globals; no allocations) ----------------
__device__ float d_dist[(size_t)Bsz * Npt * Npt];   // 268 MB distance matrix
__device__ float d_xcat[Bsz * 192 * Npt];           // x1|x2|x3 concatenated
__device__ float d_A[Bsz * 64 * Npt];
__device__ float d_Cc[Bsz * 64 * Npt];
__device__ float d_y4[Bsz * 512 * Npt];
__device__ float d_y5[Bsz * 512 * Npt];
__device__ float d_y6[Bsz * 256 * Npt];
__device__ float d_y7[Bsz * 128 * Npt];
__device__ float d_sq[Bsz * Npt];
__device__ int   d_idx[Bsz * Npt * KNN];
__device__ float d_mean[512];
__device__ float d_rstd[512];
__device__ float d_gmax[Bsz * 512];
__device__ float d_bias5[Bsz * 512];
__device__ float d_W2a[64 * 64], d_W2d[64 * 64], d_W3a[64 * 64], d_W3d[64 * 64];

__device__ __forceinline__ float lrelu(float v) { return v >= 0.f ? v : 0.2f * v; }

// ---------------- conv1: 3 -> 64 ----------------
__global__ void k_conv1(const float* __restrict__ x, const float* __restrict__ W1) {
    int n = blockIdx.x * 256 + threadIdx.x;
    int o = blockIdx.y, b = blockIdx.z;
    float v = W1[o * 3 + 0] * x[(b * 3 + 0) * Npt + n]
            + W1[o * 3 + 1] * x[(b * 3 + 1) * Npt + n]
            + W1[o * 3 + 2] * x[(b * 3 + 2) * Npt + n];
    d_xcat[((long)b * 192 + o) * Npt + n] = v;
}

// ---------------- per-channel BN stats over (b, n) ----------------
__global__ void k_stats(const float* __restrict__ buf, int CT, int c0) {
    int o = blockIdx.x;
    double s = 0.0, s2 = 0.0;
    for (int i = threadIdx.x; i < Bsz * Npt; i += 256) {
        int b = i >> 12, n = i & (Npt - 1);
        float v = buf[((long)b * CT + c0 + o) * Npt + n];
        s += v; s2 += (double)v * (double)v;
    }
    __shared__ double sh[256], sh2[256];
    sh[threadIdx.x] = s; sh2[threadIdx.x] = s2; __syncthreads();
    for (int st = 128; st > 0; st >>= 1) {
        if (threadIdx.x < st) { sh[threadIdx.x] += sh[threadIdx.x + st]; sh2[threadIdx.x] += sh2[threadIdx.x + st]; }
        __syncthreads();
    }
    if (threadIdx.x == 0) {
        double cnt = (double)(Bsz * Npt);
        double m = sh[0] / cnt;
        double var = sh2[0] / cnt - m * m;
        d_mean[o] = (float)m;
        d_rstd[o] = rsqrtf((float)fmax(var, 0.0) + EPSBN);
    }
}

// ---------------- BN apply + lrelu (in-place capable) ----------------
__global__ void k_apply(const float* __restrict__ in, float* __restrict__ out,
                        int CTin, int c0in, int CTout, int c0out,
                        const float* __restrict__ gamma, const float* __restrict__ beta) {
    int n = blockIdx.x * 256 + threadIdx.x, o = blockIdx.y, b = blockIdx.z;
    float m = d_mean[o], r = d_rstd[o], g = gamma[o], be = beta[o];
    float v = in[((long)b * CTin + c0in + o) * Npt + n];
    out[((long)b * CTout + c0out + o) * Npt + n] = lrelu((v - m) * r * g + be);
}

// ---------------- squared norms ----------------
__global__ void k_sqnorm(int c0) {
    int n = blockIdx.x * 256 + threadIdx.x, b = blockIdx.y;
    float s = 0.f;
    #pragma unroll 8
    for (int c = 0; c < 64; c++) {
        float v = d_xcat[((long)b * 192 + c0 + c) * Npt + n];
        s += v * v;
    }
    d_sq[b * Npt + n] = s;
}

// ---------------- distance matrix: dist[b,q,m] = -s[q] + 2 x_q.x_m - s[m] ----------------
__global__ void k_dist(int c0) {
    __shared__ float Qs[16][64];
    __shared__ float Ms[16][64];
    int b = blockIdx.z, q0 = blockIdx.y * 64, n0 = blockIdx.x * 64;
    int tid = threadIdx.x, tn = tid & 15, to = tid >> 4;
    float acc[4][4] = {};
    for (int ck = 0; ck < 64; ck += 16) {
        #pragma unroll
        for (int i = tid; i < 1024; i += 256) {
            int cc = i >> 6, e = i & 63;
            long rowoff = ((long)b * 192 + c0 + ck + cc) * Npt;
            Qs[cc][e] = d_xcat[rowoff + q0 + e];
            Ms[cc][e] = d_xcat[rowoff + n0 + e];
        }
        __syncthreads();
        #pragma unroll
        for (int k = 0; k < 16; k++) {
            float4 qv = *(const float4*)&Qs[k][to * 4];
            float4 mv = *(const float4*)&Ms[k][tn * 4];
            float qa[4] = {qv.x, qv.y, qv.z, qv.w};
            float ma[4] = {mv.x, mv.y, mv.z, mv.w};
            #pragma unroll
            for (int i = 0; i < 4; i++)
                #pragma unroll
                for (int j = 0; j < 4; j++)
                    acc[i][j] += qa[i] * ma[j];
        }
        __syncthreads();
    }
    float4 sq4 = *(const float4*)&d_sq[b * Npt + n0 + tn * 4];
    float sn[4] = {sq4.x, sq4.y, sq4.z, sq4.w};
    #pragma unroll
    for (int i = 0; i < 4; i++) {
        int q = q0 + to * 4 + i;
        float sqq = d_sq[b * Npt + q];
        float4 v;
        v.x = 2.f * acc[i][0] - sqq - sn[0];
        v.y = 2.f * acc[i][1] - sqq - sn[1];
        v.z = 2.f * acc[i][2] - sqq - sn[2];
        v.w = 2.f * acc[i][3] - sqq - sn[3];
        *(float4*)&d_dist[((long)(b * Npt + q)) * Npt + n0 + tn * 4] = v;
    }
}

// ---------------- top-20 per row (warp-per-32-rows, coalesced tile staging) ----------------
__global__ void k_topk() {
    __shared__ float sh[4][32][33];
    int warp = threadIdx.x >> 5, lane = threadIdx.x & 31;
    int rowBase = blockIdx.x * 128 + warp * 32;
    float topv[20]; int topi[20];
    #pragma unroll
    for (int t = 0; t < 20; t++) { topv[t] = -FLT_MAX; topi[t] = 0; }
    float curmin = -FLT_MAX; int minpos = 0;
    for (int c0 = 0; c0 < Npt; c0 += 32) {
        #pragma unroll 8
        for (int rr = 0; rr < 32; rr++)
            sh[warp][rr][lane] = d_dist[((long)(rowBase + rr)) * Npt + c0 + lane];
        __syncwarp();
        #pragma unroll 4
        for (int j = 0; j < 32; j++) {
            float v = sh[warp][lane][j];
            if (v > curmin) {           // strict > : tie keeps earlier (lower) index
                topv[minpos] = v; topi[minpos] = c0 + j;
                curmin = topv[0]; minpos = 0;
                #pragma unroll
                for (int t = 1; t < 20; t++)
                    if (topv[t] < curmin) { curmin = topv[t]; minpos = t; }
            }
        }
        __syncwarp();
    }
    int row = rowBase + lane;
    #pragma unroll
    for (int t = 0; t < 20; t++) d_idx[row * KNN + t] = topi[t];
}

// ---------------- weight prep for edge conv: Wa = W[:, :64], Wd = W[:,64:] - W[:, :64] ----------------
__global__ void k_prepw(const float* __restrict__ W, float* __restrict__ Wa, float* __restrict__ Wd) {
    int o = blockIdx.x, c = threadIdx.x;
    float a = W[o * 128 + c], bb = W[o * 128 + 64 + c];
    Wa[o * 64 + c] = a; Wd[o * 64 + c] = bb - a;
}

// ---------------- generic tiled GEMM: out[b,o,n] = sum_c W[o,c] in[b,c,n] (+bias[b,o]) ----------------
__global__ void k_gemm(float* __restrict__ out, const float* __restrict__ in,
                       const float* __restrict__ W, const float* __restrict__ biasBO,
                       int C, int ldw, int CTin, int c0in, int CTout, int c0out) {
    __shared__ float Ws[16][68];
    __shared__ float Xs[16][64];
    int b = blockIdx.z, o0 = blockIdx.y * 64, n0 = blockIdx.x * 64;
    int tid = threadIdx.x, tn = tid & 15, to = tid >> 4;
    float acc[4][4] = {};
    const float* inB = in + ((long)b * CTin + c0in) * Npt + n0;
    for (int ck = 0; ck < C; ck += 16) {
        #pragma unroll
        for (int i = tid; i < 1024; i += 256) {
            int oo = i >> 4, cc = i & 15;
            Ws[cc][oo] = W[(long)(o0 + oo) * ldw + ck + cc];
        }
        #pragma unroll
        for (int i = tid; i < 1024; i += 256) {
            int cc = i >> 6, e = i & 63;
            Xs[cc][e] = inB[(long)(ck + cc) * Npt + e];
        }
        __syncthreads();
        #pragma unroll
        for (int k = 0; k < 16; k++) {
            float4 wv = *(const float4*)&Ws[k][to * 4];
            float4 xv = *(const float4*)&Xs[k][tn * 4];
            float wa[4] = {wv.x, wv.y, wv.z, wv.w};
            float xa[4] = {xv.x, xv.y, xv.z, xv.w};
            #pragma unroll
            for (int i = 0; i < 4; i++)
                #pragma unroll
                for (int j = 0; j < 4; j++)
                    acc[i][j] += wa[i] * xa[j];
        }
        __syncthreads();
    }
    int nb = n0 + tn * 4;
    #pragma unroll
    for (int i = 0; i < 4; i++) {
        int o = o0 + to * 4 + i;
        float bias = biasBO ? biasBO[b * 512 + o] : 0.f;
        float4 v = make_float4(acc[i][0] + bias, acc[i][1] + bias,
                               acc[i][2] + bias, acc[i][3] + bias);
        *(float4*)&out[((long)b * CTout + c0out + o) * Npt + nb] = v;
    }
}

// ---------------- edge-conv BN stats over (b, n, k) ----------------
__global__ void k_edge_stats(const float* __restrict__ A, const float* __restrict__ Cc) {
    int o = blockIdx.x;
    double s = 0.0, s2 = 0.0;
    const int TOT = Bsz * Npt * KNN;
    for (int i = threadIdx.x; i < TOT; i += 256) {
        int b = i / (Npt * KNN);
        int rem = i - b * (Npt * KNN);
        int n = rem / KNN;
        int j = d_idx[i];
        float v = A[((long)b * 64 + o) * Npt + j] + Cc[((long)b * 64 + o) * Npt + n];
        s += v; s2 += (double)v * (double)v;
    }
    __shared__ double sh[256], sh2[256];
    sh[threadIdx.x] = s; sh2[threadIdx.x] = s2; __syncthreads();
    for (int st = 128; st > 0; st >>= 1) {
        if (threadIdx.x < st) { sh[threadIdx.x] += sh[threadIdx.x + st]; sh2[threadIdx.x] += sh2[threadIdx.x + st]; }
        __syncthreads();
    }
    if (threadIdx.x == 0) {
        double cnt = (double)TOT;
        double m = sh[0] / cnt;
        double var = sh2[0] / cnt - m * m;
        d_mean[o] = (float)m;
        d_rstd[o] = rsqrtf((float)fmax(var, 0.0) + EPSBN);
    }
}

// ---------------- edge-conv BN+lrelu+max_k (gather A at neighbors) ----------------
__global__ void k_edge_apply(const float* __restrict__ A, const float* __restrict__ Cc,
                             const float* __restrict__ gamma, const float* __restrict__ beta, int c0out) {
    int n = blockIdx.x * 256 + threadIdx.x, o = blockIdx.y, b = blockIdx.z;
    float m = d_mean[o], r = d_rstd[o], g = gamma[o], be = beta[o];
    const float* Ab = A + ((long)b * 64 + o) * Npt;
    float cc = Cc[((long)b * 64 + o) * Npt + n];
    const int* ip = d_idx + (b * Npt + n) * KNN;
    float best = -FLT_MAX;
    #pragma unroll 4
    for (int k = 0; k < KNN; k++) {
        float v = Ab[ip[k]] + cc;
        v = lrelu((v - m) * r * g + be);
        best = fmaxf(best, v);
    }
    d_xcat[((long)b * 192 + c0out + o) * Npt + n] = best;
}

// ---------------- BN+lrelu+max over n for the global branch ----------------
__global__ void k_maxapply(const float* __restrict__ gamma, const float* __restrict__ beta) {
    int o = blockIdx.x, b = blockIdx.y;
    float m = d_mean[o], r = d_rstd[o], g = gamma[o], be = beta[o];
    float best = -FLT_MAX;
    for (int n = threadIdx.x; n < Npt; n += 256) {
        float v = d_y4[((long)b * 512 + o) * Npt + n];
        best = fmaxf(best, lrelu((v - m) * r * g + be));
    }
    __shared__ float sh[256];
    sh[threadIdx.x] = best; __syncthreads();
    for (int st = 128; st > 0; st >>= 1) {
        if (threadIdx.x < st) sh[threadIdx.x] = fmaxf(sh[threadIdx.x], sh[threadIdx.x + st]);
        __syncthreads();
    }
    if (threadIdx.x == 0) d_gmax[b * 512 + o] = sh[0];
}

// ---------------- fold W5[:,192:] @ broadcast(gmax) into a per-(b,o) bias ----------------
__global__ void k_bias5(const float* __restrict__ W5) {
    int t = blockIdx.x * 128 + threadIdx.x;
    int b = t >> 9, o = t & 511;
    float s = 0.f;
    #pragma unroll 8
    for (int c = 0; c < 512; c++)
        s += W5[(long)o * 704 + 192 + c] * d_gmax[b * 512 + c];
    d_bias5[b * 512 + o] = s;
}

// ---------------- final conv 128 -> 2 + bias ----------------
__global__ void k_final(const float* __restrict__ W8, const float* __restrict__ b8,
                        float* __restrict__ out) {
    int n = blockIdx.x * 256 + threadIdx.x, b = blockIdx.y;
    float s0 = b8[0], s1 = b8[1];
    #pragma unroll 8
    for (int c = 0; c < 128; c++) {
        float h = d_y7[((long)b * 128 + c) * Npt + n];
        s0 += W8[c] * h;
        s1 += W8[128 + c] * h;
    }
    out[(b * 2 + 0) * Npt + n] = s0;
    out[(b * 2 + 1) * Npt + n] = s1;
}

// ---------------- host ----------------
extern "C" void kernel_launch(void* const* d_in, const int* in_sizes, int n_in,
                              void* d_out, int out_size) {
    (void)in_sizes; (void)n_in; (void)out_size;
    const float* x   = (const float*)d_in[0];
    const float* W1  = (const float*)d_in[1];
    const float* W2  = (const float*)d_in[2];
    const float* W3  = (const float*)d_in[3];
    const float* W4  = (const float*)d_in[4];
    const float* W5  = (const float*)d_in[5];
    const float* W6  = (const float*)d_in[6];
    const float* W7  = (const float*)d_in[7];
    const float* W8  = (const float*)d_in[8];
    const float* b8  = (const float*)d_in[9];
    const float* g1 = (const float*)d_in[10], *bb1 = (const float*)d_in[11];
    const float* g2 = (const float*)d_in[12], *bb2 = (const float*)d_in[13];
    const float* g3 = (const float*)d_in[14], *bb3 = (const float*)d_in[15];
    const float* g4 = (const float*)d_in[16], *bb4 = (const float*)d_in[17];
    const float* g5 = (const float*)d_in[18], *bb5 = (const float*)d_in[19];
    const float* g6 = (const float*)d_in[20], *bb6 = (const float*)d_in[21];
    const float* g7 = (const float*)d_in[22], *bb7 = (const float*)d_in[23];

    void *pv;
    cudaGetSymbolAddress(&pv, d_xcat);  float* p_xcat = (float*)pv;
    cudaGetSymbolAddress(&pv, d_A);     float* p_A    = (float*)pv;
    cudaGetSymbolAddress(&pv, d_Cc);    float* p_Cc   = (float*)pv;
    cudaGetSymbolAddress(&pv, d_y4);    float* p_y4   = (float*)pv;
    cudaGetSymbolAddress(&pv, d_y5);    float* p_y5   = (float*)pv;
    cudaGetSymbolAddress(&pv, d_y6);    float* p_y6   = (float*)pv;
    cudaGetSymbolAddress(&pv, d_y7);    float* p_y7   = (float*)pv;
    cudaGetSymbolAddress(&pv, d_bias5); float* p_b5   = (float*)pv;
    cudaGetSymbolAddress(&pv, d_W2a);   float* p_W2a  = (float*)pv;
    cudaGetSymbolAddress(&pv, d_W2d);   float* p_W2d  = (float*)pv;
    cudaGetSymbolAddress(&pv, d_W3a);   float* p_W3a  = (float*)pv;
    cudaGetSymbolAddress(&pv, d_W3d);   float* p_W3d  = (float*)pv;

    // conv1 + BN + lrelu -> x1 (xcat[0:64))
    k_conv1<<<dim3(16, 64, 4), 256>>>(x, W1);
    k_stats<<<64, 256>>>(p_xcat, 192, 0);
    k_apply<<<dim3(16, 64, 4), 256>>>(p_xcat, p_xcat, 192, 0, 192, 0, g1, bb1);

    // kNN round 1 on x1
    k_sqnorm<<<dim3(16, 4), 256>>>(0);
    k_dist<<<dim3(64, 64, 4), 256>>>(0);
    k_topk<<<128, 128>>>();

    // edge-conv 2 -> x2 (xcat[64:128))
    k_prepw<<<64, 64>>>(W2, p_W2a, p_W2d);
    k_gemm<<<dim3(64, 1, 4), 256>>>(p_A,  p_xcat, p_W2a, nullptr, 64, 64, 192, 0, 64, 0);
    k_gemm<<<dim3(64, 1, 4), 256>>>(p_Cc, p_xcat, p_W2d, nullptr, 64, 64, 192, 0, 64, 0);
    k_edge_stats<<<64, 256>>>(p_A, p_Cc);
    k_edge_apply<<<dim3(16, 64, 4), 256>>>(p_A, p_Cc, g2, bb2, 64);

    // kNN round 2 on x2
    k_sqnorm<<<dim3(16, 4), 256>>>(64);
    k_dist<<<dim3(64, 64, 4), 256>>>(64);
    k_topk<<<128, 128>>>();

    // edge-conv 3 -> x3 (xcat[128:192))
    k_prepw<<<64, 64>>>(W3, p_W3a, p_W3d);
    k_gemm<<<dim3(64, 1, 4), 256>>>(p_A,  p_xcat, p_W3a, nullptr, 64, 64, 192, 64, 64, 0);
    k_gemm<<<dim3(64, 1, 4), 256>>>(p_Cc, p_xcat, p_W3d, nullptr, 64, 64, 192, 64, 64, 0);
    k_edge_stats<<<64, 256>>>(p_A, p_Cc);
    k_edge_apply<<<dim3(16, 64, 4), 256>>>(p_A, p_Cc, g3, bb3, 128);

    // global branch: y4 = W4 @ x3; BN; lrelu; max over n -> gmax; fold into bias5
    k_gemm<<<dim3(64, 8, 4), 256>>>(p_y4, p_xcat, W4, nullptr, 64, 64, 192, 128, 512, 0);
    k_stats<<<512, 256>>>(p_y4, 512, 0);
    k_maxapply<<<dim3(512, 4), 256>>>(g4, bb4);
    k_bias5<<<16, 128>>>(W5);

    // W5 on [x1;x2;x3] (C=192) + bias5; BN; lrelu
    k_gemm<<<dim3(64, 8, 4), 256>>>(p_y5, p_xcat, W5, p_b5, 192, 704, 192, 0, 512, 0);
    k_stats<<<512, 256>>>(p_y5, 512, 0);
    k_apply<<<dim3(16, 512, 4), 256>>>(p_y5, p_y5, 512, 0, 512, 0, g5, bb5);

    // W6
    k_gemm<<<dim3(64, 4, 4), 256>>>(p_y6, p_y5, W6, nullptr, 512, 512, 512, 0, 256, 0);
    k_stats<<<256, 256>>>(p_y6, 256, 0);
    k_apply<<<dim3(16, 256, 4), 256>>>(p_y6, p_y6, 256, 0, 256, 0, g6, bb6);

    // W7
    k_gemm<<<dim3(64, 2, 4), 256>>>(p_y7, p_y6, W7, nullptr, 256, 256, 256, 0, 128, 0);
    k_stats<<<128, 256>>>(p_y7, 128, 0);
    k_apply<<<dim3(16, 128, 4), 256>>>(p_y7, p_y7, 128, 0, 128, 0, g7, bb7);

    // final 128 -> 2
    k_final<<<dim3(16, 4), 256>>>(W8, b8, (float*)d_out);
}

// round 2
// speedup vs baseline: 1.0342x; 1.0342x over previous
#include <cuda_runtime.h>
#include <math.h>
#include <float.h>

#define Bsz 4
#define Npt 4096
#define KNN 20
#define EPSBN 1e-5f

// ---------------- scratch (device globals; no allocations) ----------------
__device__ float d_dist[(size_t)Bsz * Npt * Npt];   // 268 MB distance matrix
__device__ float d_xcat[Bsz * 192 * Npt];           // x1|x2|x3 concatenated
__device__ float d_A[Bsz * 64 * Npt];
__device__ float d_Cc[Bsz * 64 * Npt];
__device__ float d_y4[Bsz * 512 * Npt];
__device__ float d_y5[Bsz * 512 * Npt];
__device__ float d_y6[Bsz * 256 * Npt];
__device__ float d_y7[Bsz * 128 * Npt];
__device__ float d_sq[Bsz * Npt];
__device__ int   d_idx[Bsz * Npt * KNN];
__device__ float d_mean[512];
__device__ float d_rstd[512];
__device__ float d_gmax[Bsz * 512];
__device__ float d_bias5[Bsz * 512];
__device__ float d_W2a[64 * 64], d_W2d[64 * 64], d_W3a[64 * 64], d_W3d[64 * 64];

__device__ __forceinline__ float lrelu(float v) { return v >= 0.f ? v : 0.2f * v; }

// ---------------- conv1: 3 -> 64 ----------------
__global__ void k_conv1(const float* __restrict__ x, const float* __restrict__ W1) {
    int n = blockIdx.x * 256 + threadIdx.x;
    int o = blockIdx.y, b = blockIdx.z;
    float v = W1[o * 3 + 0] * x[(b * 3 + 0) * Npt + n]
            + W1[o * 3 + 1] * x[(b * 3 + 1) * Npt + n]
            + W1[o * 3 + 2] * x[(b * 3 + 2) * Npt + n];
    d_xcat[((long)b * 192 + o) * Npt + n] = v;
}

// ---------------- per-channel BN stats over (b, n) ----------------
__global__ void k_stats(const float* __restrict__ buf, int CT, int c0) {
    int o = blockIdx.x;
    double s = 0.0, s2 = 0.0;
    for (int i = threadIdx.x; i < Bsz * Npt; i += 256) {
        int b = i >> 12, n = i & (Npt - 1);
        float v = buf[((long)b * CT + c0 + o) * Npt + n];
        s += v; s2 += (double)v * (double)v;
    }
    __shared__ double sh[256], sh2[256];
    sh[threadIdx.x] = s; sh2[threadIdx.x] = s2; __syncthreads();
    for (int st = 128; st > 0; st >>= 1) {
        if (threadIdx.x < st) { sh[threadIdx.x] += sh[threadIdx.x + st]; sh2[threadIdx.x] += sh2[threadIdx.x + st]; }
        __syncthreads();
    }
    if (threadIdx.x == 0) {
        double cnt = (double)(Bsz * Npt);
        double m = sh[0] / cnt;
        double var = sh2[0] / cnt - m * m;
        d_mean[o] = (float)m;
        d_rstd[o] = rsqrtf((float)fmax(var, 0.0) + EPSBN);
    }
}

// ---------------- BN apply + lrelu (in-place capable) ----------------
__global__ void k_apply(const float* __restrict__ in, float* __restrict__ out,
                        int CTin, int c0in, int CTout, int c0out,
                        const float* __restrict__ gamma, const float* __restrict__ beta) {
    int n = blockIdx.x * 256 + threadIdx.x, o = blockIdx.y, b = blockIdx.z;
    float m = d_mean[o], r = d_rstd[o], g = gamma[o], be = beta[o];
    float v = in[((long)b * CTin + c0in + o) * Npt + n];
    out[((long)b * CTout + c0out + o) * Npt + n] = lrelu((v - m) * r * g + be);
}

// ---------------- squared norms ----------------
__global__ void k_sqnorm(int c0) {
    int n = blockIdx.x * 256 + threadIdx.x, b = blockIdx.y;
    float s = 0.f;
    #pragma unroll 8
    for (int c = 0; c < 64; c++) {
        float v = d_xcat[((long)b * 192 + c0 + c) * Npt + n];
        s += v * v;
    }
    d_sq[b * Npt + n] = s;
}

// ======== 128x128 tile, 8x8/thread distance GEMM:
// dist[b,q,m] = 2 x_q.x_m - s[q] - s[m] ========
__global__ void __launch_bounds__(256, 2) k_dist128(int c0) {
    __shared__ float Qs[16][132];
    __shared__ float Ms[16][128];
    int b = blockIdx.z, q0 = blockIdx.y * 128, n0 = blockIdx.x * 128;
    int tid = threadIdx.x, tx = tid & 15, ty = tid >> 4;
    float acc[2][2][4][4] = {};
    const float* xb = d_xcat + ((long)b * 192 + c0) * Npt;
    #pragma unroll 1
    for (int ck = 0; ck < 64; ck += 16) {
        #pragma unroll
        for (int r = 0; r < 8; r++) {
            int idx = r * 256 + tid;
            int cc = idx >> 7, e = idx & 127;
            long rowoff = (long)(ck + cc) * Npt;
            Qs[cc][e] = xb[rowoff + q0 + e];
            Ms[cc][e] = xb[rowoff + n0 + e];
        }
        __syncthreads();
        #pragma unroll
        for (int k = 0; k < 16; k++) {
            float4 a0 = *(const float4*)&Qs[k][ty * 4];
            float4 a1 = *(const float4*)&Qs[k][64 + ty * 4];
            float4 b0 = *(const float4*)&Ms[k][tx * 4];
            float4 b1 = *(const float4*)&Ms[k][64 + tx * 4];
            float aa[2][4] = {{a0.x, a0.y, a0.z, a0.w}, {a1.x, a1.y, a1.z, a1.w}};
            float bb[2][4] = {{b0.x, b0.y, b0.z, b0.w}, {b1.x, b1.y, b1.z, b1.w}};
            #pragma unroll
            for (int ii = 0; ii < 2; ii++)
                #pragma unroll
                for (int i = 0; i < 4; i++)
                    #pragma unroll
                    for (int jj = 0; jj < 2; jj++)
                        #pragma unroll
                        for (int j = 0; j < 4; j++)
                            acc[ii][jj][i][j] += aa[ii][i] * bb[jj][j];
        }
        __syncthreads();
    }
    long bN = (long)b * Npt;
    float4 s0 = *(const float4*)&d_sq[bN + n0 + tx * 4];
    float4 s1 = *(const float4*)&d_sq[bN + n0 + 64 + tx * 4];
    float sn0[4] = {s0.x, s0.y, s0.z, s0.w};
    float sn1[4] = {s1.x, s1.y, s1.z, s1.w};
    #pragma unroll
    for (int ii = 0; ii < 2; ii++) {
        #pragma unroll
        for (int i = 0; i < 4; i++) {
            int q = q0 + ii * 64 + ty * 4 + i;
            float sqq = d_sq[bN + q];
            float* row = d_dist + (bN + q) * Npt + n0;
            float4 v0, v1;
            v0.x = 2.f * acc[ii][0][i][0] - sqq - sn0[0];
            v0.y = 2.f * acc[ii][0][i][1] - sqq - sn0[1];
            v0.z = 2.f * acc[ii][0][i][2] - sqq - sn0[2];
            v0.w = 2.f * acc[ii][0][i][3] - sqq - sn0[3];
            v1.x = 2.f * acc[ii][1][i][0] - sqq - sn1[0];
            v1.y = 2.f * acc[ii][1][i][1] - sqq - sn1[1];
            v1.z = 2.f * acc[ii][1][i][2] - sqq - sn1[2];
            v1.w = 2.f * acc[ii][1][i][3] - sqq - sn1[3];
            *(float4*)&row[tx * 4] = v0;
            *(float4*)&row[64 + tx * 4] = v1;
        }
    }
}

// ======== 128x128 tile, 8x8/thread feature GEMM:
// out[b, c0out+o, n] = sum_c W[o,c] in[b, c0in+c, n] (+bias[b,o]) ========
__global__ void __launch_bounds__(256, 2) k_gemm128(
        float* __restrict__ out, const float* __restrict__ in,
        const float* __restrict__ W, const float* __restrict__ biasBO,
        int C, int ldw, int CTin, int c0in, int CTout, int c0out) {
    __shared__ float Ws[16][132];
    __shared__ float Xs[16][128];
    int b = blockIdx.z, o0 = blockIdx.y * 128, n0 = blockIdx.x * 128;
    int tid = threadIdx.x, tx = tid & 15, ty = tid >> 4;
    float acc[2][2][4][4] = {};
    const float* inB = in + ((long)b * CTin + c0in) * Npt + n0;
    #pragma unroll 1
    for (int ck = 0; ck < C; ck += 16) {
        #pragma unroll
        for (int r = 0; r < 8; r++) {
            int idx = r * 256 + tid;
            int oo = idx >> 4, cc = idx & 15;
            Ws[cc][oo] = W[(long)(o0 + oo) * ldw + ck + cc];
        }
        #pragma unroll
        for (int r = 0; r < 8; r++) {
            int idx = r * 256 + tid;
            int cc = idx >> 7, e = idx & 127;
            Xs[cc][e] = inB[(long)(ck + cc) * Npt + e];
        }
        __syncthreads();
        #pragma unroll
        for (int k = 0; k < 16; k++) {
            float4 a0 = *(const float4*)&Ws[k][ty * 4];
            float4 a1 = *(const float4*)&Ws[k][64 + ty * 4];
            float4 b0 = *(const float4*)&Xs[k][tx * 4];
            float4 b1 = *(const float4*)&Xs[k][64 + tx * 4];
            float aa[2][4] = {{a0.x, a0.y, a0.z, a0.w}, {a1.x, a1.y, a1.z, a1.w}};
            float bb[2][4] = {{b0.x, b0.y, b0.z, b0.w}, {b1.x, b1.y, b1.z, b1.w}};
            #pragma unroll
            for (int ii = 0; ii < 2; ii++)
                #pragma unroll
                for (int i = 0; i < 4; i++)
                    #pragma unroll
                    for (int jj = 0; jj < 2; jj++)
                        #pragma unroll
                        for (int j = 0; j < 4; j++)
                            acc[ii][jj][i][j] += aa[ii][i] * bb[jj][j];
        }
        __syncthreads();
    }
    #pragma unroll
    for (int ii = 0; ii < 2; ii++) {
        #pragma unroll
        for (int i = 0; i < 4; i++) {
            int o = o0 + ii * 64 + ty * 4 + i;
            float bias = biasBO ? biasBO[b * 512 + o] : 0.f;
            float* row = out + ((long)b * CTout + c0out + o) * Npt + n0;
            float4 v0, v1;
            v0.x = acc[ii][0][i][0] + bias; v0.y = acc[ii][0][i][1] + bias;
            v0.z = acc[ii][0][i][2] + bias; v0.w = acc[ii][0][i][3] + bias;
            v1.x = acc[ii][1][i][0] + bias; v1.y = acc[ii][1][i][1] + bias;
            v1.z = acc[ii][1][i][2] + bias; v1.w = acc[ii][1][i][3] + bias;
            *(float4*)&row[tx * 4] = v0;
            *(float4*)&row[64 + tx * 4] = v1;
        }
    }
}

// ---------------- top-20 per row (warp-per-32-rows, coalesced tile staging) ----------------
__global__ void k_topk() {
    __shared__ float sh[4][32][33];
    int warp = threadIdx.x >> 5, lane = threadIdx.x & 31;
    int rowBase = blockIdx.x * 128 + warp * 32;
    float topv[20]; int topi[20];
    #pragma unroll
    for (int t = 0; t < 20; t++) { topv[t] = -FLT_MAX; topi[t] = 0; }
    float curmin = -FLT_MAX; int minpos = 0;
    for (int c0 = 0; c0 < Npt; c0 += 32) {
        #pragma unroll 8
        for (int rr = 0; rr < 32; rr++)
            sh[warp][rr][lane] = d_dist[((long)(rowBase + rr)) * Npt + c0 + lane];
        __syncwarp();
        #pragma unroll 4
        for (int j = 0; j < 32; j++) {
            float v = sh[warp][lane][j];
            if (v > curmin) {           // strict > : tie keeps earlier (lower) index
                topv[minpos] = v; topi[minpos] = c0 + j;
                curmin = topv[0]; minpos = 0;
                #pragma unroll
                for (int t = 1; t < 20; t++)
                    if (topv[t] < curmin) { curmin = topv[t]; minpos = t; }
            }
        }
        __syncwarp();
    }
    int row = rowBase + lane;
    #pragma unroll
    for (int t = 0; t < 20; t++) d_idx[row * KNN + t] = topi[t];
}

// ---------------- weight prep for edge conv: Wa = W[:, :64], Wd = W[:,64:] - W[:, :64] ----------------
__global__ void k_prepw(const float* __restrict__ W, float* __restrict__ Wa, float* __restrict__ Wd) {
    int o = blockIdx.x, c = threadIdx.x;
    float a = W[o * 128 + c], bb = W[o * 128 + 64 + c];
    Wa[o * 64 + c] = a; Wd[o * 64 + c] = bb - a;
}

// ---------------- generic tiled GEMM (64x64): used for small O=64 GEMMs ----------------
__global__ void k_gemm(float* __restrict__ out, const float* __restrict__ in,
                       const float* __restrict__ W, const float* __restrict__ biasBO,
                       int C, int ldw, int CTin, int c0in, int CTout, int c0out) {
    __shared__ float Ws[16][68];
    __shared__ float Xs[16][64];
    int b = blockIdx.z, o0 = blockIdx.y * 64, n0 = blockIdx.x * 64;
    int tid = threadIdx.x, tn = tid & 15, to = tid >> 4;
    float acc[4][4] = {};
    const float* inB = in + ((long)b * CTin + c0in) * Npt + n0;
    for (int ck = 0; ck < C; ck += 16) {
        #pragma unroll
        for (int i = tid; i < 1024; i += 256) {
            int oo = i >> 4, cc = i & 15;
            Ws[cc][oo] = W[(long)(o0 + oo) * ldw + ck + cc];
        }
        #pragma unroll
        for (int i = tid; i < 1024; i += 256) {
            int cc = i >> 6, e = i & 63;
            Xs[cc][e] = inB[(long)(ck + cc) * Npt + e];
        }
        __syncthreads();
        #pragma unroll
        for (int k = 0; k < 16; k++) {
            float4 wv = *(const float4*)&Ws[k][to * 4];
            float4 xv = *(const float4*)&Xs[k][tn * 4];
            float wa[4] = {wv.x, wv.y, wv.z, wv.w};
            float xa[4] = {xv.x, xv.y, xv.z, xv.w};
            #pragma unroll
            for (int i = 0; i < 4; i++)
                #pragma unroll
                for (int j = 0; j < 4; j++)
                    acc[i][j] += wa[i] * xa[j];
        }
        __syncthreads();
    }
    int nb = n0 + tn * 4;
    #pragma unroll
    for (int i = 0; i < 4; i++) {
        int o = o0 + to * 4 + i;
        float bias = biasBO ? biasBO[b * 512 + o] : 0.f;
        float4 v = make_float4(acc[i][0] + bias, acc[i][1] + bias,
                               acc[i][2] + bias, acc[i][3] + bias);
        *(float4*)&out[((long)b * CTout + c0out + o) * Npt + nb] = v;
    }
}

// ---------------- edge-conv BN stats over (b, n, k) ----------------
__global__ void k_edge_stats(const float* __restrict__ A, const float* __restrict__ Cc) {
    int o = blockIdx.x;
    double s = 0.0, s2 = 0.0;
    const int TOT = Bsz * Npt * KNN;
    for (int i = threadIdx.x; i < TOT; i += 256) {
        int b = i / (Npt * KNN);
        int rem = i - b * (Npt * KNN);
        int n = rem / KNN;
        int j = d_idx[i];
        float v = A[((long)b * 64 + o) * Npt + j] + Cc[((long)b * 64 + o) * Npt + n];
        s += v; s2 += (double)v * (double)v;
    }
    __shared__ double sh[256], sh2[256];
    sh[threadIdx.x] = s; sh2[threadIdx.x] = s2; __syncthreads();
    for (int st = 128; st > 0; st >>= 1) {
        if (threadIdx.x < st) { sh[threadIdx.x] += sh[threadIdx.x + st]; sh2[threadIdx.x] += sh2[threadIdx.x + st]; }
        __syncthreads();
    }
    if (threadIdx.x == 0) {
        double cnt = (double)TOT;
        double m = sh[0] / cnt;
        double var = sh2[0] / cnt - m * m;
        d_mean[o] = (float)m;
        d_rstd[o] = rsqrtf((float)fmax(var, 0.0) + EPSBN);
    }
}

// ---------------- edge-conv BN+lrelu+max_k (gather A at neighbors) ----------------
__global__ void k_edge_apply(const float* __restrict__ A, const float* __restrict__ Cc,
                             const float* __restrict__ gamma, const float* __restrict__ beta, int c0out) {
    int n = blockIdx.x * 256 + threadIdx.x, o = blockIdx.y, b = blockIdx.z;
    float m = d_mean[o], r = d_rstd[o], g = gamma[o], be = beta[o];
    const float* Ab = A + ((long)b * 64 + o) * Npt;
    float cc = Cc[((long)b * 64 + o) * Npt + n];
    const int* ip = d_idx + (b * Npt + n) * KNN;
    float best = -FLT_MAX;
    #pragma unroll 4
    for (int k = 0; k < KNN; k++) {
        float v = Ab[ip[k]] + cc;
        v = lrelu((v - m) * r * g + be);
        best = fmaxf(best, v);
    }
    d_xcat[((long)b * 192 + c0out + o) * Npt + n] = best;
}

// ---------------- BN+lrelu+max over n for the global branch ----------------
__global__ void k_maxapply(const float* __restrict__ gamma, const float* __restrict__ beta) {
    int o = blockIdx.x, b = blockIdx.y;
    float m = d_mean[o], r = d_rstd[o], g = gamma[o], be = beta[o];
    float best = -FLT_MAX;
    for (int n = threadIdx.x; n < Npt; n += 256) {
        float v = d_y4[((long)b * 512 + o) * Npt + n];
        best = fmaxf(best, lrelu((v - m) * r * g + be));
    }
    __shared__ float sh[256];
    sh[threadIdx.x] = best; __syncthreads();
    for (int st = 128; st > 0; st >>= 1) {
        if (threadIdx.x < st) sh[threadIdx.x] = fmaxf(sh[threadIdx.x], sh[threadIdx.x + st]);
        __syncthreads();
    }
    if (threadIdx.x == 0) d_gmax[b * 512 + o] = sh[0];
}

// ---------------- fold W5[:,192:] @ broadcast(gmax) into a per-(b,o) bias ----------------
__global__ void k_bias5(const float* __restrict__ W5) {
    int t = blockIdx.x * 128 + threadIdx.x;
    int b = t >> 9, o = t & 511;
    float s = 0.f;
    #pragma unroll 8
    for (int c = 0; c < 512; c++)
        s += W5[(long)o * 704 + 192 + c] * d_gmax[b * 512 + c];
    d_bias5[b * 512 + o] = s;
}

// ---------------- final conv 128 -> 2 + bias ----------------
__global__ void k_final(const float* __restrict__ W8, const float* __restrict__ b8,
                        float* __restrict__ out) {
    int n = blockIdx.x * 256 + threadIdx.x, b = blockIdx.y;
    float s0 = b8[0], s1 = b8[1];
    #pragma unroll 8
    for (int c = 0; c < 128; c++) {
        float h = d_y7[((long)b * 128 + c) * Npt + n];
        s0 += W8[c] * h;
        s1 += W8[128 + c] * h;
    }
    out[(b * 2 + 0) * Npt + n] = s0;
    out[(b * 2 + 1) * Npt + n] = s1;
}

// ---------------- host ----------------
extern "C" void kernel_launch(void* const* d_in, const int* in_sizes, int n_in,
                              void* d_out, int out_size) {
    (void)in_sizes; (void)n_in; (void)out_size;
    const float* x   = (const float*)d_in[0];
    const float* W1  = (const float*)d_in[1];
    const float* W2  = (const float*)d_in[2];
    const float* W3  = (const float*)d_in[3];
    const float* W4  = (const float*)d_in[4];
    const float* W5  = (const float*)d_in[5];
    const float* W6  = (const float*)d_in[6];
    const float* W7  = (const float*)d_in[7];
    const float* W8  = (const float*)d_in[8];
    const float* b8  = (const float*)d_in[9];
    const float* g1 = (const float*)d_in[10], *bb1 = (const float*)d_in[11];
    const float* g2 = (const float*)d_in[12], *bb2 = (const float*)d_in[13];
    const float* g3 = (const float*)d_in[14], *bb3 = (const float*)d_in[15];
    const float* g4 = (const float*)d_in[16], *bb4 = (const float*)d_in[17];
    const float* g5 = (const float*)d_in[18], *bb5 = (const float*)d_in[19];
    const float* g6 = (const float*)d_in[20], *bb6 = (const float*)d_in[21];
    const float* g7 = (const float*)d_in[22], *bb7 = (const float*)d_in[23];

    void *pv;
    cudaGetSymbolAddress(&pv, d_xcat);  float* p_xcat = (float*)pv;
    cudaGetSymbolAddress(&pv, d_A);     float* p_A    = (float*)pv;
    cudaGetSymbolAddress(&pv, d_Cc);    float* p_Cc   = (float*)pv;
    cudaGetSymbolAddress(&pv, d_y4);    float* p_y4   = (float*)pv;
    cudaGetSymbolAddress(&pv, d_y5);    float* p_y5   = (float*)pv;
    cudaGetSymbolAddress(&pv, d_y6);    float* p_y6   = (float*)pv;
    cudaGetSymbolAddress(&pv, d_y7);    float* p_y7   = (float*)pv;
    cudaGetSymbolAddress(&pv, d_bias5); float* p_b5   = (float*)pv;
    cudaGetSymbolAddress(&pv, d_W2a);   float* p_W2a  = (float*)pv;
    cudaGetSymbolAddress(&pv, d_W2d);   float* p_W2d  = (float*)pv;
    cudaGetSymbolAddress(&pv, d_W3a);   float* p_W3a  = (float*)pv;
    cudaGetSymbolAddress(&pv, d_W3d);   float* p_W3d  = (float*)pv;

    // conv1 + BN + lrelu -> x1 (xcat[0:64))
    k_conv1<<<dim3(16, 64, 4), 256>>>(x, W1);
    k_stats<<<64, 256>>>(p_xcat, 192, 0);
    k_apply<<<dim3(16, 64, 4), 256>>>(p_xcat, p_xcat, 192, 0, 192, 0, g1, bb1);

    // kNN round 1 on x1
    k_sqnorm<<<dim3(16, 4), 256>>>(0);
    k_dist128<<<dim3(32, 32, 4), 256>>>(0);
    k_topk<<<128, 128>>>();

    // edge-conv 2 -> x2 (xcat[64:128))
    k_prepw<<<64, 64>>>(W2, p_W2a, p_W2d);
    k_gemm<<<dim3(64, 1, 4), 256>>>(p_A,  p_xcat, p_W2a, nullptr, 64, 64, 192, 0, 64, 0);
    k_gemm<<<dim3(64, 1, 4), 256>>>(p_Cc, p_xcat, p_W2d, nullptr, 64, 64, 192, 0, 64, 0);
    k_edge_stats<<<64, 256>>>(p_A, p_Cc);
    k_edge_apply<<<dim3(16, 64, 4), 256>>>(p_A, p_Cc, g2, bb2, 64);

    // kNN round 2 on x2
    k_sqnorm<<<dim3(16, 4), 256>>>(64);
    k_dist128<<<dim3(32, 32, 4), 256>>>(64);
    k_topk<<<128, 128>>>();

    // edge-conv 3 -> x3 (xcat[128:192))
    k_prepw<<<64, 64>>>(W3, p_W3a, p_W3d);
    k_gemm<<<dim3(64, 1, 4), 256>>>(p_A,  p_xcat, p_W3a, nullptr, 64, 64, 192, 64, 64, 0);
    k_gemm<<<dim3(64, 1, 4), 256>>>(p_Cc, p_xcat, p_W3d, nullptr, 64, 64, 192, 64, 64, 0);
    k_edge_stats<<<64, 256>>>(p_A, p_Cc);
    k_edge_apply<<<dim3(16, 64, 4), 256>>>(p_A, p_Cc, g3, bb3, 128);

    // global branch: y4 = W4 @ x3; BN; lrelu; max over n -> gmax; fold into bias5
    k_gemm128<<<dim3(32, 4, 4), 256>>>(p_y4, p_xcat, W4, nullptr, 64, 64, 192, 128, 512, 0);
    k_stats<<<512, 256>>>(p_y4, 512, 0);
    k_maxapply<<<dim3(512, 4), 256>>>(g4, bb4);
    k_bias5<<<16, 128>>>(W5);

    // W5 on [x1;x2;x3] (C=192) + bias5; BN; lrelu
    k_gemm128<<<dim3(32, 4, 4), 256>>>(p_y5, p_xcat, W5, p_b5, 192, 704, 192, 0, 512, 0);
    k_stats<<<512, 256>>>(p_y5, 512, 0);
    k_apply<<<dim3(16, 512, 4), 256>>>(p_y5, p_y5, 512, 0, 512, 0, g5, bb5);

    // W6
    k_gemm128<<<dim3(32, 2, 4), 256>>>(p_y6, p_y5, W6, nullptr, 512, 512, 512, 0, 256, 0);
    k_stats<<<256, 256>>>(p_y6, 256, 0);
    k_apply<<<dim3(16, 256, 4), 256>>>(p_y6, p_y6, 256, 0, 256, 0, g6, bb6);

    // W7
    k_gemm128<<<dim3(32, 1, 4), 256>>>(p_y7, p_y6, W7, nullptr, 256, 256, 256, 0, 128, 0);
    k_stats<<<128, 256>>>(p_y7, 128, 0);
    k_apply<<<dim3(16, 128, 4), 256>>>(p_y7, p_y7, 128, 0, 128, 0, g7, bb7);

    // final 128 -> 2
    k_final<<<dim3(16, 4), 256>>>(W8, b8, (float*)d_out);
}

// round 3
// speedup vs baseline: 1.5116x; 1.4615x over previous
#include <cuda_runtime.h>
#include <math.h>
#include <float.h>

#define Bsz 4
#define Npt 4096
#define KNN 20
#define EPSBN 1e-5f
#define PARTS 4
#define PCOLS 1024
#define NROWS (Bsz * Npt)

// ---------------- scratch (device globals; no allocations) ----------------
__device__ float d_dist[(size_t)Bsz * Npt * Npt];   // 268 MB distance matrix
__device__ float d_xcat[Bsz * 192 * Npt];           // x1|x2|x3 concatenated
__device__ float d_A[Bsz * 64 * Npt];
__device__ float d_Cc[Bsz * 64 * Npt];
__device__ float d_y5[Bsz * 512 * Npt];
__device__ float d_y4[Bsz * 512 * Npt];
__device__ float d_y6[Bsz * 256 * Npt];
__device__ float d_y7[Bsz * 128 * Npt];
__device__ float d_sq[Bsz * Npt];
__device__ int   d_idx[Bsz * Npt * KNN];
__device__ float d_mean[512];
__device__ float d_rstd[512];
__device__ float d_gmax[Bsz * 512];
__device__ float d_bias5[Bsz * 512];
__device__ float d_W2a[64 * 64], d_W2d[64 * 64], d_W3a[64 * 64], d_W3d[64 * 64];
__device__ float d_ptv[PARTS * KNN * NROWS];
__device__ int   d_pti[PARTS * KNN * NROWS];

__device__ __forceinline__ float lrelu(float v) { return v >= 0.f ? v : 0.2f * v; }

// ---------------- conv1: 3 -> 64 ----------------
__global__ void k_conv1(const float* __restrict__ x, const float* __restrict__ W1) {
    int n = blockIdx.x * 256 + threadIdx.x;
    int o = blockIdx.y, b = blockIdx.z;
    float v = W1[o * 3 + 0] * x[(b * 3 + 0) * Npt + n]
            + W1[o * 3 + 1] * x[(b * 3 + 1) * Npt + n]
            + W1[o * 3 + 2] * x[(b * 3 + 2) * Npt + n];
    d_xcat[((long)b * 192 + o) * Npt + n] = v;
}

// ---------------- fused BN stats + apply + lrelu (in place) ----------------
__global__ void k_statsapply(float* __restrict__ buf, int CT, int c0,
                             const float* __restrict__ gamma, const float* __restrict__ beta) {
    int o = blockIdx.x;
    double s = 0.0, s2 = 0.0;
    for (int i = threadIdx.x; i < Bsz * Npt; i += 256) {
        int b = i >> 12, n = i & (Npt - 1);
        float v = buf[((long)b * CT + c0 + o) * Npt + n];
        s += v; s2 += (double)v * (double)v;
    }
    __shared__ double sh[256], sh2[256];
    __shared__ float smv, srv;
    sh[threadIdx.x] = s; sh2[threadIdx.x] = s2; __syncthreads();
    for (int st = 128; st > 0; st >>= 1) {
        if (threadIdx.x < st) { sh[threadIdx.x] += sh[threadIdx.x + st]; sh2[threadIdx.x] += sh2[threadIdx.x + st]; }
        __syncthreads();
    }
    if (threadIdx.x == 0) {
        double cnt = (double)(Bsz * Npt);
        double m = sh[0] / cnt;
        double var = sh2[0] / cnt - m * m;
        smv = (float)m;
        srv = rsqrtf((float)fmax(var, 0.0) + EPSBN);
    }
    __syncthreads();
    float m = smv, r = srv, g = gamma[o], be = beta[o];
    for (int i = threadIdx.x; i < Bsz * Npt; i += 256) {
        int b = i >> 12, n = i & (Npt - 1);
        long off = ((long)b * CT + c0 + o) * Npt + n;
        buf[off] = lrelu((buf[off] - m) * r * g + be);
    }
}

// ---------------- squared norms ----------------
__global__ void k_sqnorm(int c0) {
    int n = blockIdx.x * 256 + threadIdx.x, b = blockIdx.y;
    float s = 0.f;
    #pragma unroll 8
    for (int c = 0; c < 64; c++) {
        float v = d_xcat[((long)b * 192 + c0 + c) * Npt + n];
        s += v * v;
    }
    d_sq[b * Npt + n] = s;
}

// ======== 128x128 tile, 8x8/thread distance GEMM ========
__global__ void __launch_bounds__(256, 1) k_dist128(int c0) {
    __shared__ float Qs[16][132];
    __shared__ float Ms[16][128];
    int b = blockIdx.z, q0 = blockIdx.y * 128, n0 = blockIdx.x * 128;
    int tid = threadIdx.x, tx = tid & 15, ty = tid >> 4;
    float acc[2][2][4][4] = {};
    const float* xb = d_xcat + ((long)b * 192 + c0) * Npt;
    #pragma unroll 1
    for (int ck = 0; ck < 64; ck += 16) {
        #pragma unroll
        for (int r = 0; r < 8; r++) {
            int idx = r * 256 + tid;
            int cc = idx >> 7, e = idx & 127;
            long rowoff = (long)(ck + cc) * Npt;
            Qs[cc][e] = xb[rowoff + q0 + e];
            Ms[cc][e] = xb[rowoff + n0 + e];
        }
        __syncthreads();
        #pragma unroll
        for (int k = 0; k < 16; k++) {
            float4 a0 = *(const float4*)&Qs[k][ty * 4];
            float4 a1 = *(const float4*)&Qs[k][64 + ty * 4];
            float4 b0 = *(const float4*)&Ms[k][tx * 4];
            float4 b1 = *(const float4*)&Ms[k][64 + tx * 4];
            float aa[2][4] = {{a0.x, a0.y, a0.z, a0.w}, {a1.x, a1.y, a1.z, a1.w}};
            float bb[2][4] = {{b0.x, b0.y, b0.z, b0.w}, {b1.x, b1.y, b1.z, b1.w}};
            #pragma unroll
            for (int ii = 0; ii < 2; ii++)
                #pragma unroll
                for (int i = 0; i < 4; i++)
                    #pragma unroll
                    for (int jj = 0; jj < 2; jj++)
                        #pragma unroll
                        for (int j = 0; j < 4; j++)
                            acc[ii][jj][i][j] += aa[ii][i] * bb[jj][j];
        }
        __syncthreads();
    }
    long bN = (long)b * Npt;
    float4 s0 = *(const float4*)&d_sq[bN + n0 + tx * 4];
    float4 s1 = *(const float4*)&d_sq[bN + n0 + 64 + tx * 4];
    float sn0[4] = {s0.x, s0.y, s0.z, s0.w};
    float sn1[4] = {s1.x, s1.y, s1.z, s1.w};
    #pragma unroll
    for (int ii = 0; ii < 2; ii++) {
        #pragma unroll
        for (int i = 0; i < 4; i++) {
            int q = q0 + ii * 64 + ty * 4 + i;
            float sqq = d_sq[bN + q];
            float* row = d_dist + (bN + q) * Npt + n0;
            float4 v0, v1;
            v0.x = 2.f * acc[ii][0][i][0] - sqq - sn0[0];
            v0.y = 2.f * acc[ii][0][i][1] - sqq - sn0[1];
            v0.z = 2.f * acc[ii][0][i][2] - sqq - sn0[2];
            v0.w = 2.f * acc[ii][0][i][3] - sqq - sn0[3];
            v1.x = 2.f * acc[ii][1][i][0] - sqq - sn1[0];
            v1.y = 2.f * acc[ii][1][i][1] - sqq - sn1[1];
            v1.z = 2.f * acc[ii][1][i][2] - sqq - sn1[2];
            v1.w = 2.f * acc[ii][1][i][3] - sqq - sn1[3];
            *(float4*)&row[tx * 4] = v0;
            *(float4*)&row[64 + tx * 4] = v1;
        }
    }
}

// ======== 128x128 tile feature GEMM ========
__global__ void __launch_bounds__(256, 1) k_gemm128(
        float* __restrict__ out, const float* __restrict__ in,
        const float* __restrict__ W, const float* __restrict__ biasBO,
        int C, int ldw, int CTin, int c0in, int CTout, int c0out) {
    __shared__ float Ws[16][132];
    __shared__ float Xs[16][128];
    int b = blockIdx.z, o0 = blockIdx.y * 128, n0 = blockIdx.x * 128;
    int tid = threadIdx.x, tx = tid & 15, ty = tid >> 4;
    float acc[2][2][4][4] = {};
    const float* inB = in + ((long)b * CTin + c0in) * Npt + n0;
    #pragma unroll 1
    for (int ck = 0; ck < C; ck += 16) {
        #pragma unroll
        for (int r = 0; r < 8; r++) {
            int idx = r * 256 + tid;
            int oo = idx >> 4, cc = idx & 15;
            Ws[cc][oo] = W[(long)(o0 + oo) * ldw + ck + cc];
        }
        #pragma unroll
        for (int r = 0; r < 8; r++) {
            int idx = r * 256 + tid;
            int cc = idx >> 7, e = idx & 127;
            Xs[cc][e] = inB[(long)(ck + cc) * Npt + e];
        }
        __syncthreads();
        #pragma unroll
        for (int k = 0; k < 16; k++) {
            float4 a0 = *(const float4*)&Ws[k][ty * 4];
            float4 a1 = *(const float4*)&Ws[k][64 + ty * 4];
            float4 b0 = *(const float4*)&Xs[k][tx * 4];
            float4 b1 = *(const float4*)&Xs[k][64 + tx * 4];
            float aa[2][4] = {{a0.x, a0.y, a0.z, a0.w}, {a1.x, a1.y, a1.z, a1.w}};
            float bb[2][4] = {{b0.x, b0.y, b0.z, b0.w}, {b1.x, b1.y, b1.z, b1.w}};
            #pragma unroll
            for (int ii = 0; ii < 2; ii++)
                #pragma unroll
                for (int i = 0; i < 4; i++)
                    #pragma unroll
                    for (int jj = 0; jj < 2; jj++)
                        #pragma unroll
                        for (int j = 0; j < 4; j++)
                            acc[ii][jj][i][j] += aa[ii][i] * bb[jj][j];
        }
        __syncthreads();
    }
    #pragma unroll
    for (int ii = 0; ii < 2; ii++) {
        #pragma unroll
        for (int i = 0; i < 4; i++) {
            int o = o0 + ii * 64 + ty * 4 + i;
            float bias = biasBO ? biasBO[b * 512 + o] : 0.f;
            float* row = out + ((long)b * CTout + c0out + o) * Npt + n0;
            float4 v0, v1;
            v0.x = acc[ii][0][i][0] + bias; v0.y = acc[ii][0][i][1] + bias;
            v0.z = acc[ii][0][i][2] + bias; v0.w = acc[ii][0][i][3] + bias;
            v1.x = acc[ii][1][i][0] + bias; v1.y = acc[ii][1][i][1] + bias;
            v1.z = acc[ii][1][i][2] + bias; v1.w = acc[ii][1][i][3] + bias;
            *(float4*)&row[tx * 4] = v0;
            *(float4*)&row[64 + tx * 4] = v1;
        }
    }
}

// ---------------- partial top-20: each warp handles 32 rows over 1024 columns ----------------
__global__ void k_topk_part() {
    __shared__ float sh[4][32][33];
    int warp = threadIdx.x >> 5, lane = threadIdx.x & 31;
    int wg = blockIdx.x * 4 + warp;        // 0..2047
    int part = wg & 3;
    int rowBase = (wg >> 2) * 32;
    int c0base = part * PCOLS;
    float topv[20]; int topi[20];
    #pragma unroll
    for (int t = 0; t < 20; t++) { topv[t] = -FLT_MAX; topi[t] = c0base; }
    float curmin = -FLT_MAX; int minpos = 0;
    for (int c0 = c0base; c0 < c0base + PCOLS; c0 += 32) {
        #pragma unroll 8
        for (int rr = 0; rr < 32; rr++)
            sh[warp][rr][lane] = d_dist[((long)(rowBase + rr)) * Npt + c0 + lane];
        __syncwarp();
        #pragma unroll 4
        for (int j = 0; j < 32; j++) {
            float v = sh[warp][lane][j];
            if (v > curmin) {
                topv[minpos] = v; topi[minpos] = c0 + j;
                curmin = topv[0]; minpos = 0;
                #pragma unroll
                for (int t = 1; t < 20; t++)
                    if (topv[t] < curmin) { curmin = topv[t]; minpos = t; }
            }
        }
        __syncwarp();
    }
    int row = rowBase + lane;
    #pragma unroll
    for (int t = 0; t < 20; t++) {
        d_ptv[(part * 20 + t) * NROWS + row] = topv[t];
        d_pti[(part * 20 + t) * NROWS + row] = topi[t];
    }
}

// ---------------- merge 4 partial top-20 lists (ascending part order keeps ties) ----------------
__global__ void k_topk_merge() {
    int row = blockIdx.x * 256 + threadIdx.x;
    float topv[20]; int topi[20];
    #pragma unroll
    for (int t = 0; t < 20; t++) { topv[t] = -FLT_MAX; topi[t] = 0; }
    float curmin = -FLT_MAX; int minpos = 0;
    for (int p = 0; p < PARTS; p++) {
        #pragma unroll
        for (int t = 0; t < 20; t++) {
            float v = d_ptv[(p * 20 + t) * NROWS + row];
            int ix = d_pti[(p * 20 + t) * NROWS + row];
            if (v > curmin) {
                topv[minpos] = v; topi[minpos] = ix;
                curmin = topv[0]; minpos = 0;
                #pragma unroll
                for (int u = 1; u < 20; u++)
                    if (topv[u] < curmin) { curmin = topv[u]; minpos = u; }
            }
        }
    }
    #pragma unroll
    for (int t = 0; t < 20; t++) d_idx[row * KNN + t] = topi[t];
}

// ---------------- weight prep for edge conv ----------------
__global__ void k_prepw(const float* __restrict__ W, float* __restrict__ Wa, float* __restrict__ Wd) {
    int o = blockIdx.x, c = threadIdx.x;
    float a = W[o * 128 + c], bb = W[o * 128 + 64 + c];
    Wa[o * 64 + c] = a; Wd[o * 64 + c] = bb - a;
}

// ---------------- 64x64 tiled GEMM for O=64 edge convs ----------------
__global__ void k_gemm(float* __restrict__ out, const float* __restrict__ in,
                       const float* __restrict__ W, int C, int ldw,
                       int CTin, int c0in, int CTout, int c0out) {
    __shared__ float Ws[16][68];
    __shared__ float Xs[16][64];
    int b = blockIdx.z, o0 = blockIdx.y * 64, n0 = blockIdx.x * 64;
    int tid = threadIdx.x, tn = tid & 15, to = tid >> 4;
    float acc[4][4] = {};
    const float* inB = in + ((long)b * CTin + c0in) * Npt + n0;
    for (int ck = 0; ck < C; ck += 16) {
        #pragma unroll
        for (int i = tid; i < 1024; i += 256) {
            int oo = i >> 4, cc = i & 15;
            Ws[cc][oo] = W[(long)(o0 + oo) * ldw + ck + cc];
        }
        #pragma unroll
        for (int i = tid; i < 1024; i += 256) {
            int cc = i >> 6, e = i & 63;
            Xs[cc][e] = inB[(long)(ck + cc) * Npt + e];
        }
        __syncthreads();
        #pragma unroll
        for (int k = 0; k < 16; k++) {
            float4 wv = *(const float4*)&Ws[k][to * 4];
            float4 xv = *(const float4*)&Xs[k][tn * 4];
            float wa[4] = {wv.x, wv.y, wv.z, wv.w};
            float xa[4] = {xv.x, xv.y, xv.z, xv.w};
            #pragma unroll
            for (int i = 0; i < 4; i++)
                #pragma unroll
                for (int j = 0; j < 4; j++)
                    acc[i][j] += wa[i] * xa[j];
        }
        __syncthreads();
    }
    int nb = n0 + tn * 4;
    #pragma unroll
    for (int i = 0; i < 4; i++) {
        int o = o0 + to * 4 + i;
        float4 v = make_float4(acc[i][0], acc[i][1], acc[i][2], acc[i][3]);
        *(float4*)&out[((long)b * CTout + c0out + o) * Npt + nb] = v;
    }
}

// ---------------- edge-conv BN stats over (b, n, k) ----------------
__global__ void k_edge_stats(const float* __restrict__ A, const float* __restrict__ Cc) {
    int o = blockIdx.x;
    double s = 0.0, s2 = 0.0;
    const int TOT = Bsz * Npt * KNN;
    for (int i = threadIdx.x; i < TOT; i += 256) {
        int b = i / (Npt * KNN);
        int rem = i - b * (Npt * KNN);
        int n = rem / KNN;
        int j = d_idx[i];
        float v = A[((long)b * 64 + o) * Npt + j] + Cc[((long)b * 64 + o) * Npt + n];
        s += v; s2 += (double)v * (double)v;
    }
    __shared__ double sh[256], sh2[256];
    sh[threadIdx.x] = s; sh2[threadIdx.x] = s2; __syncthreads();
    for (int st = 128; st > 0; st >>= 1) {
        if (threadIdx.x < st) { sh[threadIdx.x] += sh[threadIdx.x + st]; sh2[threadIdx.x] += sh2[threadIdx.x + st]; }
        __syncthreads();
    }
    if (threadIdx.x == 0) {
        double cnt = (double)TOT;
        double m = sh[0] / cnt;
        double var = sh2[0] / cnt - m * m;
        d_mean[o] = (float)m;
        d_rstd[o] = rsqrtf((float)fmax(var, 0.0) + EPSBN);
    }
}

// ---------------- edge-conv BN+lrelu+max_k ----------------
__global__ void k_edge_apply(const float* __restrict__ A, const float* __restrict__ Cc,
                             const float* __restrict__ gamma, const float* __restrict__ beta, int c0out) {
    int n = blockIdx.x * 256 + threadIdx.x, o = blockIdx.y, b = blockIdx.z;
    float m = d_mean[o], r = d_rstd[o], g = gamma[o], be = beta[o];
    const float* Ab = A + ((long)b * 64 + o) * Npt;
    float cc = Cc[((long)b * 64 + o) * Npt + n];
    const int* ip = d_idx + (b * Npt + n) * KNN;
    float best = -FLT_MAX;
    #pragma unroll 4
    for (int k = 0; k < KNN; k++) {
        float v = Ab[ip[k]] + cc;
        v = lrelu((v - m) * r * g + be);
        best = fmaxf(best, v);
    }
    d_xcat[((long)b * 192 + c0out + o) * Npt + n] = best;
}

// ---------------- fused stats + BN + lrelu + max over n -> gmax ----------------
__global__ void k_stats_gmax(const float* __restrict__ buf,
                             const float* __restrict__ gamma, const float* __restrict__ beta) {
    int o = blockIdx.x;  // 512
    double s = 0.0, s2 = 0.0;
    for (int i = threadIdx.x; i < Bsz * Npt; i += 256) {
        int b = i >> 12, n = i & (Npt - 1);
        float v = buf[((long)b * 512 + o) * Npt + n];
        s += v; s2 += (double)v * (double)v;
    }
    __shared__ double sh[256], sh2[256];
    __shared__ float smv, srv;
    sh[threadIdx.x] = s; sh2[threadIdx.x] = s2; __syncthreads();
    for (int st = 128; st > 0; st >>= 1) {
        if (threadIdx.x < st) { sh[threadIdx.x] += sh[threadIdx.x + st]; sh2[threadIdx.x] += sh2[threadIdx.x + st]; }
        __syncthreads();
    }
    if (threadIdx.x == 0) {
        double cnt = (double)(Bsz * Npt);
        double m = sh[0] / cnt;
        double var = sh2[0] / cnt - m * m;
        smv = (float)m;
        srv = rsqrtf((float)fmax(var, 0.0) + EPSBN);
    }
    __syncthreads();
    float m = smv, r = srv, g = gamma[o], be = beta[o];
    __shared__ float shm[256];
    for (int b = 0; b < Bsz; b++) {
        float best = -FLT_MAX;
        for (int n = threadIdx.x; n < Npt; n += 256) {
            float v = buf[((long)b * 512 + o) * Npt + n];
            best = fmaxf(best, lrelu((v - m) * r * g + be));
        }
        shm[threadIdx.x] = best; __syncthreads();
        for (int st = 128; st > 0; st >>= 1) {
            if (threadIdx.x < st) shm[threadIdx.x] = fmaxf(shm[threadIdx.x], shm[threadIdx.x + st]);
            __syncthreads();
        }
        if (threadIdx.x == 0) d_gmax[b * 512 + o] = shm[0];
        __syncthreads();
    }
}

// ---------------- fold W5[:,192:] @ broadcast(gmax) into a per-(b,o) bias ----------------
__global__ void k_bias5(const float* __restrict__ W5) {
    int t = blockIdx.x * 128 + threadIdx.x;
    int b = t >> 9, o = t & 511;
    float s = 0.f;
    #pragma unroll 8
    for (int c = 0; c < 512; c++)
        s += W5[(long)o * 704 + 192 + c] * d_gmax[b * 512 + c];
    d_bias5[b * 512 + o] = s;
}

// ---------------- final conv 128 -> 2 + bias ----------------
__global__ void k_final(const float* __restrict__ W8, const float* __restrict__ b8,
                        float* __restrict__ out) {
    int n = blockIdx.x * 256 + threadIdx.x, b = blockIdx.y;
    float s0 = b8[0], s1 = b8[1];
    #pragma unroll 8
    for (int c = 0; c < 128; c++) {
        float h = d_y7[((long)b * 128 + c) * Npt + n];
        s0 += W8[c] * h;
        s1 += W8[128 + c] * h;
    }
    out[(b * 2 + 0) * Npt + n] = s0;
    out[(b * 2 + 1) * Npt + n] = s1;
}

// ---------------- host ----------------
extern "C" void kernel_launch(void* const* d_in, const int* in_sizes, int n_in,
                              void* d_out, int out_size) {
    (void)in_sizes; (void)n_in; (void)out_size;
    const float* x   = (const float*)d_in[0];
    const float* W1  = (const float*)d_in[1];
    const float* W2  = (const float*)d_in[2];
    const float* W3  = (const float*)d_in[3];
    const float* W4  = (const float*)d_in[4];
    const float* W5  = (const float*)d_in[5];
    const float* W6  = (const float*)d_in[6];
    const float* W7  = (const float*)d_in[7];
    const float* W8  = (const float*)d_in[8];
    const float* b8  = (const float*)d_in[9];
    const float* g1 = (const float*)d_in[10], *bb1 = (const float*)d_in[11];
    const float* g2 = (const float*)d_in[12], *bb2 = (const float*)d_in[13];
    const float* g3 = (const float*)d_in[14], *bb3 = (const float*)d_in[15];
    const float* g4 = (const float*)d_in[16], *bb4 = (const float*)d_in[17];
    const float* g5 = (const float*)d_in[18], *bb5 = (const float*)d_in[19];
    const float* g6 = (const float*)d_in[20], *bb6 = (const float*)d_in[21];
    const float* g7 = (const float*)d_in[22], *bb7 = (const float*)d_in[23];

    void *pv;
    cudaGetSymbolAddress(&pv, d_xcat);  float* p_xcat = (float*)pv;
    cudaGetSymbolAddress(&pv, d_A);     float* p_A    = (float*)pv;
    cudaGetSymbolAddress(&pv, d_Cc);    float* p_Cc   = (float*)pv;
    cudaGetSymbolAddress(&pv, d_y4);    float* p_y4   = (float*)pv;
    cudaGetSymbolAddress(&pv, d_y5);    float* p_y5   = (float*)pv;
    cudaGetSymbolAddress(&pv, d_y6);    float* p_y6   = (float*)pv;
    cudaGetSymbolAddress(&pv, d_y7);    float* p_y7   = (float*)pv;
    cudaGetSymbolAddress(&pv, d_bias5); float* p_b5   = (float*)pv;
    cudaGetSymbolAddress(&pv, d_W2a);   float* p_W2a  = (float*)pv;
    cudaGetSymbolAddress(&pv, d_W2d);   float* p_W2d  = (float*)pv;
    cudaGetSymbolAddress(&pv, d_W3a);   float* p_W3a  = (float*)pv;
    cudaGetSymbolAddress(&pv, d_W3d);   float* p_W3d  = (float*)pv;

    // conv1 + BN + lrelu -> x1 (xcat[0:64))
    k_conv1<<<dim3(16, 64, 4), 256>>>(x, W1);
    k_statsapply<<<64, 256>>>(p_xcat, 192, 0, g1, bb1);

    // kNN round 1 on x1
    k_sqnorm<<<dim3(16, 4), 256>>>(0);
    k_dist128<<<dim3(32, 32, 4), 256>>>(0);
    k_topk_part<<<512, 128>>>();
    k_topk_merge<<<64, 256>>>();

    // edge-conv 2 -> x2 (xcat[64:128))
    k_prepw<<<64, 64>>>(W2, p_W2a, p_W2d);
    k_gemm<<<dim3(64, 1, 4), 256>>>(p_A,  p_xcat, p_W2a, 64, 64, 192, 0, 64, 0);
    k_gemm<<<dim3(64, 1, 4), 256>>>(p_Cc, p_xcat, p_W2d, 64, 64, 192, 0, 64, 0);
    k_edge_stats<<<64, 256>>>(p_A, p_Cc);
    k_edge_apply<<<dim3(16, 64, 4), 256>>>(p_A, p_Cc, g2, bb2, 64);

    // kNN round 2 on x2
    k_sqnorm<<<dim3(16, 4), 256>>>(64);
    k_dist128<<<dim3(32, 32, 4), 256>>>(64);
    k_topk_part<<<512, 128>>>();
    k_topk_merge<<<64, 256>>>();

    // edge-conv 3 -> x3 (xcat[128:192))
    k_prepw<<<64, 64>>>(W3, p_W3a, p_W3d);
    k_gemm<<<dim3(64, 1, 4), 256>>>(p_A,  p_xcat, p_W3a, 64, 64, 192, 64, 64, 0);
    k_gemm<<<dim3(64, 1, 4), 256>>>(p_Cc, p_xcat, p_W3d, 64, 64, 192, 64, 64, 0);
    k_edge_stats<<<64, 256>>>(p_A, p_Cc);
    k_edge_apply<<<dim3(16, 64, 4), 256>>>(p_A, p_Cc, g3, bb3, 128);

    // global branch: y4 = W4 @ x3; fused stats+BN+lrelu+max -> gmax; fold into bias5
    k_gemm128<<<dim3(32, 4, 4), 256>>>(p_y4, p_xcat, W4, nullptr, 64, 64, 192, 128, 512, 0);
    k_stats_gmax<<<512, 256>>>(p_y4, g4, bb4);
    k_bias5<<<16, 128>>>(W5);

    // W5 on [x1;x2;x3] (C=192) + bias5; BN; lrelu
    k_gemm128<<<dim3(32, 4, 4), 256>>>(p_y5, p_xcat, W5, p_b5, 192, 704, 192, 0, 512, 0);
    k_statsapply<<<512, 256>>>(p_y5, 512, 0, g5, bb5);

    // W6
    k_gemm128<<<dim3(32, 2, 4), 256>>>(p_y6, p_y5, W6, nullptr, 512, 512, 512, 0, 256, 0);
    k_statsapply<<<256, 256>>>(p_y6, 256, 0, g6, bb6);

    // W7
    k_gemm128<<<dim3(32, 1, 4), 256>>>(p_y7, p_y6, W7, nullptr, 256, 256, 256, 0, 128, 0);
    k_statsapply<<<128, 256>>>(p_y7, 128, 0, g7, bb7);

    // final 128 -> 2
    k_final<<<dim3(16, 4), 256>>>(W8, b8, (float*)d_out);
}